// round 1
// baseline (speedup 1.0000x reference)
#include <cuda_runtime.h>
#include <math.h>

#define G_      256
#define NATOMS  32
#define DD      41
#define NRAD    4
#define NCOEF   16
#define NOUT    64
#define CHUNKS  9
#define TPB     256

__global__ void zero_kernel(float* out, int n) {
    int i = blockIdx.x * blockDim.x + threadIdx.x;
    if (i < n) out[i] = 0.0f;
}

__launch_bounds__(TPB, 2)
__global__ void project_kernel(const float* __restrict__ rho,
                               const float* __restrict__ positions,
                               const float* __restrict__ Wmat,
                               const int*   __restrict__ offs,
                               float*       __restrict__ out)
{
    const int atom  = blockIdx.x / CHUNKS;
    const int chunk = blockIdx.x % CHUNKS;

    __shared__ float cX[DD], cY[DD], cZ[DD];
    __shared__ int   iX[DD], iY[DD], iZ[DD];
    __shared__ float red[NOUT];

    const int t = threadIdx.x;

    // Per-dimension window setup: coords (A*off - dr) and wrapped grid indices,
    // with x/y indices pre-shifted into their linear-address bit positions.
    if (t < 3 * DD) {
        const float Af = (float)(25.6 / 256.0);   // A as f32 (0.1f), matches JAX f32 math
        int d = t / DD, s = t % DD;
        float p   = positions[atom * 3 + d];
        float cmf = rintf(p / Af);                 // round-half-even == jnp.round
        float dr  = p - Af * cmf;
        int   cm  = (int)cmf;
        int   off = offs[s];
        float coord = Af * (float)off;
        float c = coord - dr;
        int idx = (off + cm) & (G_ - 1);           // G=256 -> mod is a mask
        if (d == 0)      { cX[s] = c; iX[s] = idx << 16; }
        else if (d == 1) { cY[s] = c; iY[s] = idx << 8;  }
        else             { cZ[s] = c; iZ[s] = idx;       }
    }
    if (t < NOUT) red[t] = 0.0f;
    __syncthreads();

    // 64 raw accumulators: M[a][c] = sum over points of g_a(R) * Y_c(u,v,w) * rho
    float acc[NRAD][NCOEF];
    #pragma unroll
    for (int a = 0; a < NRAD; a++)
        #pragma unroll
        for (int c = 0; c < NCOEF; c++) acc[a][c] = 0.0f;

    const int TOT = DD * DD * DD;                  // 68921
    const int q0 = (int)(((long long)TOT * chunk)       / CHUNKS);
    const int q1 = (int)(((long long)TOT * (chunk + 1)) / CHUNKS);

    for (int q = q0 + t; q < q1; q += TPB) {
        int i = q / (DD * DD);
        int r = q - i * (DD * DD);
        int j = r / DD;
        int k = r - j * DD;
        float X = cX[i], Y = cY[j], Z = cZ[k];
        float r2 = fmaf(X, X, fmaf(Y, Y, Z * Z));
        if (r2 < 4.0f) {                           // R < R_O (= 2.0)
            float srho = __ldg(rho + (iX[i] + iY[j] + iZ[k]));
            float rinv, R;
            if (r2 > 1e-30f) { rinv = rsqrtf(r2); R = r2 * rinv; }
            else             { rinv = 0.0f;       R = 0.0f;      }

            // raw radials (normalization 1/Nn folded into final mix)
            float tt = 2.0f - R;
            float t2 = tt * tt;
            float g0 = r2 * t2;
            float g1 = g0 * tt, g2 = g1 * tt, g3 = g2 * tt;

            // real spherical harmonics up to l=3, Cartesian form (no trig)
            float u = X * rinv, v = Y * rinv, w = Z * rinv;
            float u2 = u * u, v2 = v * v, w2 = w * w;
            float Yv[NCOEF];
            Yv[0]  = 0.28209479177387814f;
            Yv[1]  = 0.48860251190291992f * v;
            Yv[2]  = 0.48860251190291992f * w;
            Yv[3]  = 0.48860251190291992f * u;
            Yv[4]  = 1.09254843059207907f * u * v;
            Yv[5]  = 1.09254843059207907f * v * w;
            Yv[6]  = 0.31539156525252005f * (3.0f * w2 - 1.0f);
            Yv[7]  = 1.09254843059207907f * u * w;
            Yv[8]  = 0.54627421529603959f * (u2 - v2);
            Yv[9]  = 0.59004358992664352f * v * (3.0f * u2 - v2);
            Yv[10] = 2.89061144264055405f * u * v * w;
            Yv[11] = 0.45704579946446577f * v * (5.0f * w2 - 1.0f);
            Yv[12] = 0.37317633259011546f * w * (5.0f * w2 - 3.0f);
            Yv[13] = 0.45704579946446577f * u * (5.0f * w2 - 1.0f);
            Yv[14] = 1.44530572132027735f * w * (u2 - v2);
            Yv[15] = 0.59004358992664352f * u * (u2 - 3.0f * v2);

            float gr0 = g0 * srho, gr1 = g1 * srho, gr2 = g2 * srho, gr3 = g3 * srho;
            #pragma unroll
            for (int c = 0; c < NCOEF; c++) {
                acc[0][c] = fmaf(gr0, Yv[c], acc[0][c]);
                acc[1][c] = fmaf(gr1, Yv[c], acc[1][c]);
                acc[2][c] = fmaf(gr2, Yv[c], acc[2][c]);
                acc[3][c] = fmaf(gr3, Yv[c], acc[3][c]);
            }
        }
    }

    // Reduce 64 sums across the block: warp butterfly, then shared atomics.
    #pragma unroll
    for (int a = 0; a < NRAD; a++) {
        #pragma unroll
        for (int c = 0; c < NCOEF; c++) {
            float val = acc[a][c];
            #pragma unroll
            for (int o = 16; o > 0; o >>= 1)
                val += __shfl_down_sync(0xffffffffu, val, o);
            if ((t & 31) == 0) atomicAdd(&red[a * NCOEF + c], val);
        }
    }
    __syncthreads();

    // Final mix: out[n][c] = V_CELL * sum_a W[n][a] * (1/Nn_a) * M[a][c]
    if (t < NOUT) {
        int n = t >> 4, c = t & 15;
        const double dens[4]  = {1474560.0, 5898240.0, 23592960.0, 94371840.0};   // 720*2^(11+2a)
        const double prods[4] = {1663200.0, 8648640.0, 32432400.0, 98017920.0};   // prod(2a+k, k=5..11)
        const double Ad = 25.6 / 256.0;
        const float  vcell = (float)(Ad * Ad * Ad);
        float s = 0.0f;
        #pragma unroll
        for (int a = 0; a < NRAD; a++) {
            float invNn = (float)sqrt(prods[a] / dens[a]);
            s += Wmat[n * 4 + a] * invNn * red[a * NCOEF + c];
        }
        atomicAdd(&out[atom * NOUT + t], s * vcell);
    }
}

extern "C" void kernel_launch(void* const* d_in, const int* in_sizes, int n_in,
                              void* d_out, int out_size) {
    const float* rho  = (const float*)d_in[0];
    const float* pos  = (const float*)d_in[1];
    const float* W    = (const float*)d_in[2];
    const int*   offs = (const int*)d_in[3];
    float* out = (float*)d_out;

    zero_kernel<<<(NATOMS * NOUT + 255) / 256, 256>>>(out, NATOMS * NOUT);
    project_kernel<<<NATOMS * CHUNKS, TPB>>>(rho, pos, W, offs, out);
}

// round 2
// speedup vs baseline: 1.2538x; 1.2538x over previous
#include <cuda_runtime.h>
#include <math.h>

#define G_      256
#define NATOMS  32
#define DD      41
#define NRAD    4
#define NCOEF   16
#define NOUT    64
#define CHUNKS  9
#define TPB     256
#define UNR     4

typedef unsigned long long u64;

__device__ __forceinline__ u64 pack2(float lo, float hi) {
    u64 r; asm("mov.b64 %0, {%1,%2};" : "=l"(r) : "f"(lo), "f"(hi)); return r;
}
__device__ __forceinline__ void unpack2(u64 p, float& lo, float& hi) {
    asm("mov.b64 {%0,%1}, %2;" : "=f"(lo), "=f"(hi) : "l"(p));
}
__device__ __forceinline__ void fma2(u64& d, u64 a, u64 b) {
    asm("fma.rn.f32x2 %0, %1, %2, %0;" : "+l"(d) : "l"(a), "l"(b));
}
__device__ __forceinline__ u64 add2(u64 a, u64 b) {
    u64 r; asm("add.rn.f32x2 %0, %1, %2;" : "=l"(r) : "l"(a), "l"(b)); return r;
}

__global__ void zero_kernel(float* out, int n) {
    int i = blockIdx.x * blockDim.x + threadIdx.x;
    if (i < n) out[i] = 0.0f;
}

__launch_bounds__(TPB, 2)
__global__ void project_kernel(const float* __restrict__ rho,
                               const float* __restrict__ positions,
                               const float* __restrict__ Wmat,
                               const int*   __restrict__ offs,
                               float*       __restrict__ out)
{
    const int atom  = blockIdx.x / CHUNKS;
    const int chunk = blockIdx.x % CHUNKS;

    // .x = coord (A*off - dr), .y = grid index (pre-shifted) as bits
    __shared__ float2 sX[DD], sY[DD], sZ[DD];
    __shared__ float  red[NOUT];

    const int t = threadIdx.x;

    if (t < 3 * DD) {
        const float Af = 0.1f;                     // A = 25.6/256 exactly
        int d = t / DD, s = t % DD;
        float p   = positions[atom * 3 + d];
        float cmf = rintf(p / Af);                 // round-half-even == jnp.round
        float dr  = p - Af * cmf;
        int   cm  = (int)cmf;
        int   off = offs[s];
        float c   = Af * (float)off - dr;
        int   idx = (off + cm) & (G_ - 1);
        if (d == 0)      sX[s] = make_float2(c, __int_as_float(idx << 16));
        else if (d == 1) sY[s] = make_float2(c, __int_as_float(idx << 8));
        else             sZ[s] = make_float2(c, __int_as_float(idx));
    }
    if (t < NOUT) red[t] = 0.0f;
    __syncthreads();

    // Packed accumulators: acc2[a][h] holds (M[a][2h], M[a][2h+1])
    u64 acc2[NRAD][NCOEF / 2];
    #pragma unroll
    for (int a = 0; a < NRAD; a++)
        #pragma unroll
        for (int h = 0; h < NCOEF / 2; h++) acc2[a][h] = 0ull;

    // Round-robin slab assignment: this block handles slabs i = chunk + 9*s
    const int nslabs = (DD - chunk + CHUNKS - 1) / CHUNKS;   // 5 or 4
    const int NP = nslabs * DD * DD;

    for (int base = t; base < NP; base += TPB * UNR) {
        float Xp[UNR], Yp[UNR], Zp[UNR], r2p[UNR], srp[UNR];
        bool  okp[UNR];
        // Phase 1: decode + batched loads (MLP = UNR)
        #pragma unroll
        for (int u = 0; u < UNR; u++) {
            int m = base + u * TPB;
            bool inb = m < NP;
            int mm = inb ? m : 0;
            int il = mm / (DD * DD);
            int r  = mm - il * (DD * DD);
            int j  = r / DD;
            int k  = r - j * DD;
            int i  = chunk + CHUNKS * il;
            float2 px = sX[i], py = sY[j], pz = sZ[k];
            float X = px.x, Y = py.x, Z = pz.x;
            int addr = __float_as_int(px.y) + __float_as_int(py.y) + __float_as_int(pz.y);
            float r2 = fmaf(X, X, fmaf(Y, Y, Z * Z));
            srp[u] = __ldg(rho + addr);            // unconditional: keeps loads batched
            Xp[u] = X; Yp[u] = Y; Zp[u] = Z; r2p[u] = r2;
            okp[u] = inb && (r2 < 4.0f);
        }
        // Phase 2: heavy compute per in-sphere point
        #pragma unroll
        for (int u = 0; u < UNR; u++) {
            if (!okp[u]) continue;
            float r2 = r2p[u], X = Xp[u], Y = Yp[u], Z = Zp[u], srho = srp[u];
            float rinv = (r2 > 1e-30f) ? rsqrtf(r2) : 0.0f;
            float R = r2 * rinv;

            float tt = 2.0f - R;
            float g0 = r2 * tt * tt;
            float g1 = g0 * tt, g2 = g1 * tt, g3 = g2 * tt;

            float u_ = X * rinv, v_ = Y * rinv, w_ = Z * rinv;
            float u2 = u_ * u_, v2 = v_ * v_, w2 = w_ * w_;
            float uv = u_ * v_;
            float f5w1 = fmaf(5.0f, w2, -1.0f);
            float umv  = u2 - v2;

            float Yv[NCOEF];
            Yv[0]  = 0.28209479177387814f;
            Yv[1]  = 0.48860251190291992f * v_;
            Yv[2]  = 0.48860251190291992f * w_;
            Yv[3]  = 0.48860251190291992f * u_;
            Yv[4]  = 1.09254843059207907f * uv;
            Yv[5]  = 1.09254843059207907f * (v_ * w_);
            Yv[6]  = 0.31539156525252005f * fmaf(3.0f, w2, -1.0f);
            Yv[7]  = 1.09254843059207907f * (u_ * w_);
            Yv[8]  = 0.54627421529603959f * umv;
            Yv[9]  = 0.59004358992664352f * (v_ * fmaf(3.0f, u2, -v2));
            Yv[10] = 2.89061144264055405f * (uv * w_);
            Yv[11] = 0.45704579946446577f * (v_ * f5w1);
            Yv[12] = 0.37317633259011546f * (w_ * fmaf(5.0f, w2, -3.0f));
            Yv[13] = 0.45704579946446577f * (u_ * f5w1);
            Yv[14] = 1.44530572132027735f * (w_ * umv);
            Yv[15] = 0.59004358992664352f * (u_ * fmaf(u2, 1.0f, -3.0f * v2));

            u64 Ypk[NCOEF / 2];
            #pragma unroll
            for (int h = 0; h < NCOEF / 2; h++) Ypk[h] = pack2(Yv[2 * h], Yv[2 * h + 1]);

            float gr0 = g0 * srho, gr1 = g1 * srho, gr2 = g2 * srho, gr3 = g3 * srho;
            u64 gp0 = pack2(gr0, gr0), gp1 = pack2(gr1, gr1);
            u64 gp2 = pack2(gr2, gr2), gp3 = pack2(gr3, gr3);

            #pragma unroll
            for (int h = 0; h < NCOEF / 2; h++) {
                fma2(acc2[0][h], gp0, Ypk[h]);
                fma2(acc2[1][h], gp1, Ypk[h]);
                fma2(acc2[2][h], gp2, Ypk[h]);
                fma2(acc2[3][h], gp3, Ypk[h]);
            }
        }
    }

    // Block reduction: packed warp butterfly -> shared atomics
    #pragma unroll
    for (int a = 0; a < NRAD; a++) {
        #pragma unroll
        for (int h = 0; h < NCOEF / 2; h++) {
            u64 v = acc2[a][h];
            #pragma unroll
            for (int o = 16; o > 0; o >>= 1)
                v = add2(v, __shfl_down_sync(0xffffffffu, v, o));
            if ((t & 31) == 0) {
                float lo, hi;
                unpack2(v, lo, hi);
                atomicAdd(&red[a * NCOEF + 2 * h],     lo);
                atomicAdd(&red[a * NCOEF + 2 * h + 1], hi);
            }
        }
    }
    __syncthreads();

    // Final mix: out[n][c] = V_CELL * sum_a W[n][a] * (1/Nn_a) * M[a][c]
    if (t < NOUT) {
        int n = t >> 4, c = t & 15;
        const double dens[4]  = {1474560.0, 5898240.0, 23592960.0, 94371840.0};
        const double prods[4] = {1663200.0, 8648640.0, 32432400.0, 98017920.0};
        const double Ad = 25.6 / 256.0;
        const float  vcell = (float)(Ad * Ad * Ad);
        float s = 0.0f;
        #pragma unroll
        for (int a = 0; a < NRAD; a++) {
            float invNn = (float)sqrt(prods[a] / dens[a]);
            s += Wmat[n * 4 + a] * invNn * red[a * NCOEF + c];
        }
        atomicAdd(&out[atom * NOUT + t], s * vcell);
    }
}

extern "C" void kernel_launch(void* const* d_in, const int* in_sizes, int n_in,
                              void* d_out, int out_size) {
    const float* rho  = (const float*)d_in[0];
    const float* pos  = (const float*)d_in[1];
    const float* W    = (const float*)d_in[2];
    const int*   offs = (const int*)d_in[3];
    float* out = (float*)d_out;

    zero_kernel<<<(NATOMS * NOUT + 255) / 256, 256>>>(out, NATOMS * NOUT);
    project_kernel<<<NATOMS * CHUNKS, TPB>>>(rho, pos, W, offs, out);
}